// round 1
// baseline (speedup 1.0000x reference)
#include <cuda_runtime.h>
#include <cuda_bf16.h>
#include <math.h>

#define N_PRIORS   268800
#define CAP        16384
#define T_SEL      0.95f
#define MAX_KEEP   750
#define IOU_THR    0.4f
#define NSLICE     16
#define SLICE      (CAP / NSLICE)   // 1024

// ---------------- device scratch (no allocation allowed) ----------------
__device__ int                g_cnt;
__device__ int                g_nkeep;
__device__ unsigned long long g_keys[CAP];     // (score_bits<<32) | (0xFFFFFFFF - idx)
__device__ int                g_rank[CAP];
__device__ float4             g_cbox[CAP];     // sorted candidate boxes
__device__ float              g_carea[CAP];
__device__ int                g_cidx[CAP];     // sorted candidate prior index
__device__ int                g_keep[MAX_KEEP];

// ---------------- prior / decode helpers ----------------
__device__ __forceinline__ void prior_of(int g, float& pcx, float& pcy, float& ps) {
    int step, f, msbase, r;
    if (g < 204800)      { step = 8;  f = 320; msbase = 16;  r = g; }
    else if (g < 256000) { step = 16; f = 160; msbase = 64;  r = g - 204800; }
    else                 { step = 32; f = 80;  msbase = 256; r = g - 256000; }
    int m = r & 1;
    int c = r >> 1;
    int y = c / f;
    int x = c - y * f;
    // numpy computes in float64 then casts to float32 — replicate exactly.
    pcx = (float)(((double)x + 0.5) * (double)step / 2560.0);
    pcy = (float)(((double)y + 0.5) * (double)step / 2560.0);
    ps  = (float)((double)(msbase << m) / 2560.0);
}

__device__ __forceinline__ float4 decode_box(int idx, const float4* __restrict__ loc4,
                                             float& area) {
    float4 L = loc4[idx];
    float pcx, pcy, ps;
    prior_of(idx, pcx, pcy, ps);
    float cx = pcx + (L.x * 0.1f) * ps;
    float cy = pcy + (L.y * 0.1f) * ps;
    // exp in double -> correctly-rounded f32 (immune to --use_fast_math)
    float w = ps * (float)exp((double)(L.z * 0.2f));
    float h = ps * (float)exp((double)(L.w * 0.2f));
    float4 b;
    b.x = (cx - w * 0.5f) * 2560.0f;
    b.y = (cy - h * 0.5f) * 2560.0f;
    b.z = (cx + w * 0.5f) * 2560.0f;
    b.w = (cy + h * 0.5f) * 2560.0f;
    area = (b.z - b.x + 1.0f) * (b.w - b.y + 1.0f);
    return b;
}

__device__ __forceinline__ bool overlaps(float4 a, float aa, float4 b, float ab) {
    float xx1 = fmaxf(a.x, b.x);
    float yy1 = fmaxf(a.y, b.y);
    float xx2 = fminf(a.z, b.z);
    float yy2 = fminf(a.w, b.w);
    float iw = fmaxf(0.0f, xx2 - xx1 + 1.0f);
    float ih = fmaxf(0.0f, yy2 - yy1 + 1.0f);
    float inter = iw * ih;
    // reference: inter / (area_i + area_j - inter) > 0.4, IEEE f32 division
    return __fdiv_rn(inter, (aa + ab) - inter) > IOU_THR;
}

// ---------------- kernels ----------------
__global__ void init_kernel() {
    int i = blockIdx.x * blockDim.x + threadIdx.x;
    if (i < CAP) g_rank[i] = 0;
    if (i == 0) { g_cnt = 0; g_nkeep = 0; }
}

__global__ void filter_kernel(const float* __restrict__ scores) {
    int i = blockIdx.x * blockDim.x + threadIdx.x;
    if (i >= N_PRIORS) return;
    float s = scores[i];
    if (s > T_SEL) {
        int slot = atomicAdd(&g_cnt, 1);
        if (slot < CAP) {
            unsigned long long key =
                ((unsigned long long)__float_as_uint(s) << 32) |
                (unsigned long long)(0xFFFFFFFFu - (unsigned)i);
            g_keys[slot] = key;
        }
    }
}

// exact rank of each candidate = #keys strictly greater  (descending position)
__global__ void rank_kernel() {
    __shared__ unsigned long long sk[SLICE];
    int cnt = min(g_cnt, CAP);
    int s0 = blockIdx.y * SLICE;
    for (int j = threadIdx.x; j < SLICE; j += blockDim.x) {
        int jj = s0 + j;
        sk[j] = (jj < cnt) ? g_keys[jj] : 0ULL;
    }
    __syncthreads();
    int c = blockIdx.x * blockDim.x + threadIdx.x;
    if (c >= cnt) return;
    unsigned long long kc = g_keys[c];
    int lim = cnt - s0;
    if (lim > SLICE) lim = SLICE;
    if (lim < 0) lim = 0;
    int r = 0;
    #pragma unroll 4
    for (int j = 0; j < lim; j++) r += (sk[j] > kc) ? 1 : 0;
    if (r) atomicAdd(&g_rank[c], r);
}

__global__ void gather_kernel(const float4* __restrict__ loc4) {
    int c = blockIdx.x * blockDim.x + threadIdx.x;
    int cnt = min(g_cnt, CAP);
    if (c >= cnt) return;
    unsigned long long k = g_keys[c];
    int idx = (int)(0xFFFFFFFFu - (unsigned)(k & 0xFFFFFFFFull));
    int r = g_rank[c];
    float area;
    float4 b = decode_box(idx, loc4, area);
    g_cbox[r]  = b;
    g_carea[r] = area;
    g_cidx[r]  = idx;
}

// single-block greedy NMS scan over sorted candidates, chunks of 32
__global__ void __launch_bounds__(1024, 1) nms_kernel() {
    __shared__ float4  s_kb[MAX_KEEP];
    __shared__ float   s_ka[MAX_KEEP];
    __shared__ float4  s_cb[32];
    __shared__ float   s_ca[32];
    __shared__ int     s_extA[32];
    __shared__ unsigned s_row[32];
    __shared__ int     s_nk;
    __shared__ unsigned s_acc;
    __shared__ int     s_base_nk;

    int tid = threadIdx.x;
    int w = tid >> 5, l = tid & 31;
    int cnt = min(g_cnt, CAP);
    if (tid == 0) s_nk = 0;
    __syncthreads();

    for (int base = 0; base < cnt; base += 32) {
        // load chunk candidates
        if (tid < 32) {
            int c = base + tid;
            if (c < cnt) { s_cb[tid] = g_cbox[c]; s_ca[tid] = g_carea[c]; }
        }
        __syncthreads();
        int nk = s_nk;
        if (nk >= MAX_KEEP) break;

        // external check: warp w handles candidate w against kept list
        {
            bool sup;
            int c = base + w;
            if (c < cnt) {
                sup = false;
                float4 cb = s_cb[w];
                float  ca = s_ca[w];
                for (int k = l; k < nk; k += 32) {
                    if (overlaps(cb, ca, s_kb[k], s_ka[k])) { sup = true; break; }
                }
            } else {
                sup = true;
            }
            bool any = __any_sync(0xFFFFFFFFu, sup);
            if (l == 0) s_extA[w] = any ? 1 : 0;
        }

        // intra-chunk suppression matrix (row w: bits of earlier peers overlapping w)
        {
            bool ov = false;
            int cw = base + w, cl = base + l;
            if (cw < cnt && cl < cnt && l < w)
                ov = overlaps(s_cb[w], s_ca[w], s_cb[l], s_ca[l]);
            unsigned r = __ballot_sync(0xFFFFFFFFu, ov);
            if (l == 0) s_row[w] = r;
        }
        __syncthreads();

        // serial bitmask resolve (thread 0)
        if (tid == 0) {
            unsigned acc = 0;
            int nk2 = s_nk;
            int lim = cnt - base; if (lim > 32) lim = 32;
            for (int c = 0; c < lim && nk2 < MAX_KEEP; c++) {
                if (!s_extA[c] && !(s_row[c] & acc)) {
                    acc |= (1u << c);
                    nk2++;
                }
            }
            s_acc = acc;
            s_base_nk = s_nk;
            s_nk = nk2;
        }
        __syncthreads();

        // parallel append of accepted candidates
        if (tid < 32) {
            unsigned acc = s_acc;
            if ((acc >> tid) & 1u) {
                int pos = s_base_nk + __popc(acc & ((1u << tid) - 1u));
                s_kb[pos] = s_cb[tid];
                s_ka[pos] = s_ca[tid];
                g_keep[pos] = g_cidx[base + tid];
            }
        }
        __syncthreads();
    }
    if (tid == 0) g_nkeep = s_nk;
}

__global__ void out_kernel(const float* __restrict__ scores,
                           const float* __restrict__ landms,
                           const float4* __restrict__ loc4,
                           const float* __restrict__ thrp,
                           float* __restrict__ out) {
    int k = blockIdx.x * blockDim.x + threadIdx.x;
    if (k >= MAX_KEEP) return;
    float thr = thrp[0];
    int nk = g_nkeep;

    float bx0 = 0.f, bx1 = 0.f, bx2 = 0.f, bx3 = 0.f, sc = 0.f;
    float lm[10];
    #pragma unroll
    for (int j = 0; j < 10; j++) lm[j] = 0.f;

    if (k < nk) {
        int idx = g_keep[k];
        float s = scores[idx];
        if (s > thr) {
            float area;
            float4 b = decode_box(idx, loc4, area);
            bx0 = b.x; bx1 = b.y; bx2 = b.z; bx3 = b.w;
            sc = s;
            float pcx, pcy, ps;
            prior_of(idx, pcx, pcy, ps);
            #pragma unroll
            for (int j = 0; j < 5; j++) {
                float ox = landms[idx * 10 + 2 * j];
                float oy = landms[idx * 10 + 2 * j + 1];
                lm[2 * j]     = (pcx + (ox * 0.1f) * ps) * 2560.0f;
                lm[2 * j + 1] = (pcy + (oy * 0.1f) * ps) * 2560.0f;
            }
        }
    }
    out[k * 4 + 0] = bx0;
    out[k * 4 + 1] = bx1;
    out[k * 4 + 2] = bx2;
    out[k * 4 + 3] = bx3;
    out[MAX_KEEP * 4 + k] = sc;
    #pragma unroll
    for (int j = 0; j < 10; j++)
        out[MAX_KEEP * 4 + MAX_KEEP + k * 10 + j] = lm[j];
}

// ---------------- launch ----------------
extern "C" void kernel_launch(void* const* d_in, const int* in_sizes, int n_in,
                              void* d_out, int out_size) {
    const float* bboxes = (const float*)d_in[0];   // (1, N, 4)
    const float* scores = (const float*)d_in[1];   // (1, N)
    const float* landms = (const float*)d_in[2];   // (1, N, 10)
    const float* thrp   = (const float*)d_in[3];   // (1,)
    float* out = (float*)d_out;                    // 11250 floats

    init_kernel<<<(CAP + 255) / 256, 256>>>();
    filter_kernel<<<(N_PRIORS + 255) / 256, 256>>>(scores);
    dim3 rg((CAP + 255) / 256, NSLICE);
    rank_kernel<<<rg, 256>>>();
    gather_kernel<<<CAP / 256, 256>>>((const float4*)bboxes);
    nms_kernel<<<1, 1024>>>();
    out_kernel<<<(MAX_KEEP + 255) / 256, 256>>>(scores, landms,
                                                (const float4*)bboxes, thrp, out);
}